// round 1
// baseline (speedup 1.0000x reference)
#include <cuda_runtime.h>
#include <math.h>

#define NC 1000
#define NA 64

// Scratch for pp = rowsum(W * P). __device__ global (no allocation allowed).
__device__ float g_pp[1024];

// Kernel 1: pp[row] = sum_k W[row,k] * P[row,k].  One warp per row, float2 per lane,
// fixed-order shuffle tree => deterministic.
__global__ void pp_kernel(const float* __restrict__ W, const float* __restrict__ P) {
    int warp = (blockIdx.x * blockDim.x + threadIdx.x) >> 5;
    int lane = threadIdx.x & 31;
    if (warp >= NC) return;
    const float2* w2 = reinterpret_cast<const float2*>(W + warp * NA);
    const float2* p2 = reinterpret_cast<const float2*>(P + warp * NA);
    float2 w = w2[lane];
    float2 p = p2[lane];
    float s = w.x * p.x + w.y * p.y;
    #pragma unroll
    for (int off = 16; off; off >>= 1)
        s += __shfl_down_sync(0xffffffffu, s, off);
    if (lane == 0) g_pp[warp] = s;
}

// Kernel 2: softmax(pp) -> q; c = argmax(p0); precompute exact float omega
// sequence; evaluate match predicate for ALL iterations in parallel (warp per
// iteration); first stop index gives the output blend.
__global__ __launch_bounds__(1024) void solve_kernel(const float* __restrict__ p0,
                                                     const float* __restrict__ omega,
                                                     float* __restrict__ out) {
    __shared__ float sp0[1024];
    __shared__ float sq[1024];
    __shared__ float som[1024];     // omega sequence (n <= 1001)
    __shared__ int   sflag[1024];   // match flag per iteration
    __shared__ float sredf[32];
    __shared__ int   sredi[32];
    __shared__ float s_val[2];      // [0]=max(pp), [1]=sum(exp)
    __shared__ int   s_misc[3];     // [0]=c, [1]=n, [2]=istar

    const unsigned FULL = 0xffffffffu;
    int tid  = threadIdx.x;
    int lane = tid & 31;
    int wid  = tid >> 5;

    float p0v = (tid < NC) ? p0[tid] : 0.0f;
    sp0[tid] = p0v;
    float ppv = (tid < NC) ? g_pp[tid] : -INFINITY;

    // ---- block max(pp) ----
    {
        float m = ppv;
        #pragma unroll
        for (int off = 16; off; off >>= 1)
            m = fmaxf(m, __shfl_down_sync(FULL, m, off));
        if (lane == 0) sredf[wid] = m;
        __syncthreads();
        if (wid == 0) {
            float x = sredf[lane];
            #pragma unroll
            for (int off = 16; off; off >>= 1)
                x = fmaxf(x, __shfl_down_sync(FULL, x, off));
            if (lane == 0) s_val[0] = x;
        }
        __syncthreads();
    }
    float m = s_val[0];

    // ---- block sum(exp(pp - m)) ----
    float e = (tid < NC) ? expf(ppv - m) : 0.0f;
    {
        float s = e;
        #pragma unroll
        for (int off = 16; off; off >>= 1)
            s += __shfl_down_sync(FULL, s, off);
        if (lane == 0) sredf[wid] = s;
        __syncthreads();
        if (wid == 0) {
            float x = sredf[lane];
            #pragma unroll
            for (int off = 16; off; off >>= 1)
                x += __shfl_down_sync(FULL, x, off);
            if (lane == 0) s_val[1] = x;
        }
        __syncthreads();
    }
    float q = e / s_val[1];
    sq[tid] = q;

    // ---- c = argmax(p0), first-index tie-break (jnp.argmax semantics) ----
    {
        float av = (tid < NC) ? p0v : -INFINITY;
        int   ai = tid;
        #pragma unroll
        for (int off = 16; off; off >>= 1) {
            float ov = __shfl_down_sync(FULL, av, off);
            int   oi = __shfl_down_sync(FULL, ai, off);
            if (ov > av || (ov == av && oi < ai)) { av = ov; ai = oi; }
        }
        if (lane == 0) { sredf[wid] = av; sredi[wid] = ai; }
        __syncthreads();
        if (wid == 0) {
            float x  = sredf[lane];
            int   xi = sredi[lane];
            #pragma unroll
            for (int off = 16; off; off >>= 1) {
                float ov = __shfl_down_sync(FULL, x, off);
                int   oi = __shfl_down_sync(FULL, xi, off);
                if (ov > x || (ov == x && oi < xi)) { x = ov; xi = oi; }
            }
            if (lane == 0) s_misc[0] = xi;
        }
    }

    // ---- exact float omega sequence: w, w-0.01f, ... until dec < 0.001f ----
    if (tid == 0) {
        float w = omega[0];
        w = fminf(fmaxf(w, 0.0f), 1.0f);
        int n = 0;
        float cur = w;
        while (true) {
            som[n] = cur;
            n++;
            float dec = cur - 0.01f;
            if (dec < 0.001f || n >= 1001) break;  // underflow / MAX_ITERS
            cur = dec;
        }
        s_misc[1] = n;
    }
    __syncthreads();

    int c = s_misc[0];
    int n = s_misc[1];

    // ---- parallel match evaluation: one warp per iteration ----
    for (int i = wid; i < n; i += 32) {
        float om   = som[i];
        float onem = 1.0f - om;
        float best = -INFINITY;
        int   bidx = NC;
        for (int j = lane; j < NC; j += 32) {
            float v = onem * sp0[j] + om * sq[j];
            if (v > best) { best = v; bidx = j; }   // strict > keeps first max per lane
        }
        #pragma unroll
        for (int off = 16; off; off >>= 1) {
            float ov = __shfl_down_sync(FULL, best, off);
            int   oi = __shfl_down_sync(FULL, bidx, off);
            if (ov > best || (ov == best && oi < bidx)) { best = ov; bidx = oi; }
        }
        if (lane == 0) sflag[i] = (bidx == c) ? 1 : 0;
    }
    __syncthreads();

    // ---- first stop index: first match, else forced underflow stop at n-1 ----
    if (tid == 0) {
        int istar = n - 1;
        for (int i = 0; i < n; i++) {
            if (sflag[i]) { istar = i; break; }
        }
        s_misc[2] = istar;
    }
    __syncthreads();

    // ---- output: p = (1-omega*) * p0 + omega* * q, shape (1, NC) ----
    if (tid < NC) {
        float om = som[s_misc[2]];
        out[tid] = (1.0f - om) * sp0[tid] + om * sq[tid];
    }
}

extern "C" void kernel_launch(void* const* d_in, const int* in_sizes, int n_in,
                              void* d_out, int out_size) {
    const float* p0 = (const float*)d_in[0];
    const float* P  = (const float*)d_in[1];
    const float* W  = (const float*)d_in[2];
    const float* om = (const float*)d_in[3];
    float* out = (float*)d_out;

    // 1000 rows, 8 warps (rows) per 256-thread block -> 125 blocks.
    pp_kernel<<<125, 256>>>(W, P);
    solve_kernel<<<1, 1024>>>(p0, om, out);
}

// round 3
// speedup vs baseline: 2.0308x; 2.0308x over previous
#include <cuda_runtime.h>
#include <math.h>

#define NC 1000
#define NA 64

// Scratch for pp = rowsum(W * P). __device__ global (no allocation allowed).
__device__ float g_pp[1024];

// Kernel 1: pp[row] = sum_k W[row,k] * P[row,k].  One warp per row, float2 per
// lane, fixed-order shuffle tree => deterministic. 125 blocks -> full-chip BW.
__global__ void pp_kernel(const float* __restrict__ W, const float* __restrict__ P) {
    int warp = (blockIdx.x * blockDim.x + threadIdx.x) >> 5;
    int lane = threadIdx.x & 31;
    if (warp >= NC) return;
    const float2* w2 = reinterpret_cast<const float2*>(W + warp * NA);
    const float2* p2 = reinterpret_cast<const float2*>(P + warp * NA);
    float2 w = w2[lane];
    float2 p = p2[lane];
    float s = w.x * p.x + w.y * p.y;
    #pragma unroll
    for (int off = 16; off; off >>= 1)
        s += __shfl_down_sync(0xffffffffu, s, off);
    if (lane == 0) g_pp[warp] = s;
}

// Kernel 2: fully register-resident solver.
//   q = softmax(pp); c = argmax(p0).
//   Per class j (one thread each): t_j = first iteration of the exact float
//   omega sequence where j no longer beats c (prefix property of the linear
//   blend).  istar = max_j t_j (capped at underflow).  One int-max reduction.
__global__ __launch_bounds__(1024) void solve_kernel(const float* __restrict__ p0,
                                                     const float* __restrict__ omega,
                                                     float* __restrict__ out) {
    __shared__ float red_f[32];
    __shared__ int   red_i[32];
    __shared__ float s_maxpp, s_sumexp, s_p0c, s_qc;
    __shared__ int   s_c, s_istar;

    const unsigned FULL = 0xffffffffu;
    int tid  = threadIdx.x;
    int lane = tid & 31;
    int wid  = tid >> 5;
    bool live = (tid < NC);

    float w0 = omega[0];
    w0 = fminf(fmaxf(w0, 0.0f), 1.0f);

    float p0v = live ? p0[tid]   : -INFINITY;
    float ppv = live ? g_pp[tid] : -INFINITY;

    // ---- reduction 1: max(pp) ----
    {
        float m = ppv;
        #pragma unroll
        for (int off = 16; off; off >>= 1)
            m = fmaxf(m, __shfl_down_sync(FULL, m, off));
        if (lane == 0) red_f[wid] = m;
        __syncthreads();
        if (wid == 0) {
            float x = red_f[lane];
            #pragma unroll
            for (int off = 16; off; off >>= 1)
                x = fmaxf(x, __shfl_down_sync(FULL, x, off));
            if (lane == 0) s_maxpp = x;
        }
        __syncthreads();
    }

    // ---- reduction 2: sum(exp(pp - max)) ----
    float e = live ? expf(ppv - s_maxpp) : 0.0f;
    {
        float s = e;
        #pragma unroll
        for (int off = 16; off; off >>= 1)
            s += __shfl_down_sync(FULL, s, off);
        if (lane == 0) red_f[wid] = s;
        __syncthreads();
        if (wid == 0) {
            float x = red_f[lane];
            #pragma unroll
            for (int off = 16; off; off >>= 1)
                x += __shfl_down_sync(FULL, x, off);
            if (lane == 0) s_sumexp = x;
        }
        __syncthreads();
    }
    float qv = e / s_sumexp;

    // ---- reduction 3: c = argmax(p0), first-index tie-break ----
    {
        float av = p0v;      // -inf for dead threads
        int   ai = tid;
        #pragma unroll
        for (int off = 16; off; off >>= 1) {
            float ov = __shfl_down_sync(FULL, av, off);
            int   oi = __shfl_down_sync(FULL, ai, off);
            if (ov > av || (ov == av && oi < ai)) { av = ov; ai = oi; }
        }
        if (lane == 0) { red_f[wid] = av; red_i[wid] = ai; }
        __syncthreads();
        if (wid == 0) {
            float x  = red_f[lane];
            int   xi = red_i[lane];
            #pragma unroll
            for (int off = 16; off; off >>= 1) {
                float ov = __shfl_down_sync(FULL, x, off);
                int   oi = __shfl_down_sync(FULL, xi, off);
                if (ov > x || (ov == x && oi < xi)) { x = ov; xi = oi; }
            }
            if (lane == 0) s_c = xi;
        }
        __syncthreads();
    }
    int c = s_c;
    if (tid == c) { s_p0c = p0v; s_qc = qv; }
    __syncthreads();
    float p0c = s_p0c;
    float qc  = s_qc;

    // ---- per-class scan: t_j = first i where j does not beat c ----
    // Violation (j beats c in argmax order): j<c needs vj >= vc ; j>c needs vj > vc.
    // Exact float omega recurrence, early exit; capped at the underflow index.
    int t = 0;
    if (live && tid != c) {
        float cur = w0;
        int i = 0;
        while (true) {
            float onem = 1.0f - cur;
            float vc = onem * p0c + cur * qc;
            float vj = onem * p0v + cur * qv;
            bool viol = (tid < c) ? (vj >= vc) : (vj > vc);
            if (!viol) { t = i; break; }
            float dec = cur - 0.01f;
            if (dec < 0.001f) { t = i; break; }   // underflow: forced stop here
            cur = dec;
            ++i;
        }
    }

    // ---- reduction 4: istar = max(t) ----
    {
        int m = t;
        #pragma unroll
        for (int off = 16; off; off >>= 1)
            m = max(m, __shfl_down_sync(FULL, m, off));
        if (lane == 0) red_i[wid] = m;
        __syncthreads();
        if (wid == 0) {
            int x = red_i[lane];
            #pragma unroll
            for (int off = 16; off; off >>= 1)
                x = max(x, __shfl_down_sync(FULL, x, off));
            if (lane == 0) s_istar = x;
        }
        __syncthreads();
    }
    int istar = s_istar;

    // ---- recompute omega_istar via the exact recurrence, write output ----
    if (live) {
        float cur = w0;
        for (int k = 0; k < istar; ++k) cur = cur - 0.01f;
        float onem = 1.0f - cur;
        out[tid] = onem * p0v + cur * qv;
    }
}

extern "C" void kernel_launch(void* const* d_in, const int* in_sizes, int n_in,
                              void* d_out, int out_size) {
    const float* p0 = (const float*)d_in[0];
    const float* P  = (const float*)d_in[1];
    const float* W  = (const float*)d_in[2];
    const float* om = (const float*)d_in[3];
    float* out = (float*)d_out;

    pp_kernel<<<125, 256>>>(W, P);
    solve_kernel<<<1, 1024>>>(p0, om, out);
}